// round 1
// baseline (speedup 1.0000x reference)
#include <cuda_runtime.h>
#include <math.h>

// ---------------- problem constants ----------------
#define B_    4
#define C_    64
#define H_    256
#define W_    256
#define NPIX_ 16777216            // B*C*H*W
#define NPAT_ 4096                // patches per batch (64*64)
#define NT_   16384               // B * NPAT
#define TOK_  1024
#define SF_   2114
#define KSEL_ 1024
#define E_    128
#define NH_   4
#define DH_   32

// ---------------- device scratch (static; no runtime allocation) ----------------
__device__ float2 g_cA[NPIX_];
__device__ float2 g_cB[NPIX_];
__device__ float  g_ampV[NPIX_];
__device__ float  g_ampI[NPIX_];
__device__ float  g_phV [NPIX_];
__device__ float  g_phI [NPIX_];
__device__ float  g_faMap[NPIX_];
__device__ float  g_fpMap[NPIX_];
__device__ float  g_spatial[NPIX_];
__device__ float  g_r1[NPIX_];
__device__ float  g_feat[(long)NT_ * SF_];
__device__ float  g_hid[NT_ * 128];
__device__ float  g_scoreArr[NT_];
__device__ int    g_idxArr[B_ * KSEL_];
__device__ float  g_selV[(long)B_ * KSEL_ * TOK_];
__device__ float  g_selI[(long)B_ * KSEL_ * TOK_];
__device__ float  g_qb[B_ * KSEL_ * E_];
__device__ float  g_kb[B_ * KSEL_ * E_];
__device__ float  g_vb[B_ * KSEL_ * E_];
__device__ float  g_ob[B_ * KSEL_ * E_];
__device__ float  g_att[(long)B_ * NH_ * KSEL_ * KSEL_];   // 16,777,216
__device__ float  g_fs[(long)B_ * KSEL_ * TOK_];
__device__ float  g_gm[B_ * 2 * C_];
__device__ float  g_intentArr[B_ * 64];
__device__ float  g_twr[128];
__device__ float  g_twi[128];

// ---------------- twiddles ----------------
__global__ void twiddle_init_kernel() {
    int k = threadIdx.x;
    if (k < 128) {
        double a = -2.0 * 3.14159265358979323846 * (double)k / 256.0;
        g_twr[k] = (float)cos(a);
        g_twi[k] = (float)sin(a);
    }
}

// ---------------- 256-point FFT (radix-2 DIT, 128 threads per FFT) ----------------
__device__ __forceinline__ void fft256(float* re, float* im, int t, int dir) {
    // bit-reversal permutation
    for (int i = t; i < 256; i += 128) {
        int j = __brev((unsigned)i) >> 24;
        if (j > i) {
            float a = re[i]; re[i] = re[j]; re[j] = a;
            float b = im[i]; im[i] = im[j]; im[j] = b;
        }
    }
    __syncthreads();
    #pragma unroll
    for (int s = 1; s <= 8; s++) {
        int half = 1 << (s - 1);
        int grp = t >> (s - 1);
        int pos = t & (half - 1);
        int i = (grp << s) + pos;
        int j = i + half;
        int tw = pos << (8 - s);
        float wr = g_twr[tw];
        float wi = (dir > 0) ? g_twi[tw] : -g_twi[tw];
        float xr = re[j], xi = im[j];
        float vr = xr * wr - xi * wi;
        float vi = xr * wi + xi * wr;
        float ur = re[i], ui = im[i];
        re[i] = ur + vr; im[i] = ui + vi;
        re[j] = ur - vr; im[j] = ui - vi;
        __syncthreads();
    }
}

// One 1D FFT pass over rows (colmode=0) or columns (colmode=1) of 256x256 planes.
// rin  != null : load real input (im=0)
// rout != null : store only real part (scaled)
__global__ void fft_pass_kernel(float2* data, const float* __restrict__ rin,
                                float* __restrict__ rout, int dir, int colmode) {
    __shared__ float sre[2][256];
    __shared__ float sim[2][256];
    int slot = threadIdx.x >> 7;
    int t = threadIdx.x & 127;
    int line = blockIdx.x * 2 + slot;
    int plane = line >> 8;
    int l = line & 255;
    long base; int stride;
    if (colmode) { base = (long)plane * 65536 + l; stride = 256; }
    else         { base = (long)plane * 65536 + (long)l * 256; stride = 1; }
    float* re = sre[slot];
    float* im = sim[slot];
    if (rin) {
        for (int i = t; i < 256; i += 128) { re[i] = rin[base + (long)i * stride]; im[i] = 0.f; }
    } else {
        for (int i = t; i < 256; i += 128) {
            float2 c = data[base + (long)i * stride];
            re[i] = c.x; im[i] = c.y;
        }
    }
    __syncthreads();
    fft256(re, im, t, dir);
    float sc = (dir > 0) ? 1.0f : (1.0f / 256.0f);
    if (rout) {
        for (int i = t; i < 256; i += 128) rout[base + (long)i * stride] = re[i] * sc;
    } else {
        for (int i = t; i < 256; i += 128)
            data[base + (long)i * stride] = make_float2(re[i] * sc, im[i] * sc);
    }
}

// ---------------- amplitude / phase ----------------
__global__ void ampphase_kernel() {
    int i = blockIdx.x * 256 + threadIdx.x;
    float2 a = g_cA[i];
    float2 b = g_cB[i];
    g_ampV[i] = sqrtf(a.x * a.x + a.y * a.y);
    g_phV[i]  = atan2f(a.y, a.x);
    g_ampI[i] = sqrtf(b.x * b.x + b.y * b.y);
    g_phI[i]  = atan2f(b.y, b.x);
}

// ---------------- router ----------------
__global__ void gap_kernel(const float* __restrict__ vis, const float* __restrict__ ir,
                           float* __restrict__ gm) {
    __shared__ float red[256];
    int b = blockIdx.x >> 7;
    int ch = blockIdx.x & 127;
    const float* p = (ch < 64) ? (vis + (long)(b * 64 + ch) * 65536)
                               : (ir  + (long)(b * 64 + ch - 64) * 65536);
    float s = 0.f;
    for (int i = threadIdx.x; i < 65536; i += 256) s += p[i];
    red[threadIdx.x] = s;
    __syncthreads();
    for (int st = 128; st > 0; st >>= 1) {
        if (threadIdx.x < st) red[threadIdx.x] += red[threadIdx.x + st];
        __syncthreads();
    }
    if (threadIdx.x == 0) gm[blockIdx.x] = red[0] * (1.0f / 65536.0f);
}

__global__ void router_kernel(const float* __restrict__ gm, const float* __restrict__ Wr,
                              const float* __restrict__ br, const float* __restrict__ bank,
                              float* __restrict__ intent) {
    __shared__ float pf[4][64];
    __shared__ float lg[4][4];
    __shared__ float w[4][4];
    int t = threadIdx.x;  // 64 threads
    for (int b = 0; b < 4; b++) {
        float s = br[t];
        for (int c = 0; c < 128; c++) s += gm[b * 128 + c] * Wr[c * 64 + t];
        pf[b][t] = s;
    }
    __syncthreads();
    if (t < 16) {
        int b = t >> 2, j = t & 3;
        float s = 0.f;
        for (int p = 0; p < 64; p++) s += pf[b][p] * bank[j * 64 + p];
        lg[b][j] = s;
    }
    __syncthreads();
    if (t < 4) {
        int b = t;
        float m = fmaxf(fmaxf(lg[b][0], lg[b][1]), fmaxf(lg[b][2], lg[b][3]));
        float e0 = expf(lg[b][0] - m), e1 = expf(lg[b][1] - m);
        float e2 = expf(lg[b][2] - m), e3 = expf(lg[b][3] - m);
        float s = e0 + e1 + e2 + e3;
        w[b][0] = e0 / s; w[b][1] = e1 / s; w[b][2] = e2 / s; w[b][3] = e3 / s;
    }
    __syncthreads();
    for (int b = 0; b < 4; b++) {
        float s = 0.f;
        for (int j = 0; j < 4; j++) s += w[b][j] * bank[j * 64 + t];
        intent[b * 64 + t] = s;
    }
}

// ---------------- feature assembly ----------------
__global__ void feat_kernel(const float* __restrict__ mapV, const float* __restrict__ mapI,
                            const float* __restrict__ intent, float* __restrict__ feat) {
    int r = blockIdx.y;
    int col = blockIdx.x * 256 + threadIdx.x;
    if (col >= SF_) return;
    int b = r >> 12;
    int n = r & 4095;
    int hy = n >> 6, wx = n & 63;
    float v;
    if (col < 2048) {
        int t = col & 1023;
        int c = t >> 4, py = (t >> 2) & 3, px = t & 3;
        long m = (((long)(b * 64 + c) * 256) + hy * 4 + py) * 256 + wx * 4 + px;
        v = (col < 1024) ? mapV[m] : mapI[m];
    } else if (col == 2048) v = (float)hy * (1.0f / 63.0f);
    else if (col == 2049)   v = (float)wx * (1.0f / 63.0f);
    else                    v = intent[b * 64 + (col - 2050)];
    feat[(long)r * SF_ + col] = v;
}

// ---------------- generic fp32 GEMM: C = act(A@B + bias + residual) ----------------
// A [M,K] row-major, B [K,N] row-major, C [M,N] row-major
__global__ void gemm_kernel(const float* __restrict__ A, const float* __restrict__ Bm,
                            float* __restrict__ C, const float* __restrict__ bias,
                            const float* __restrict__ residual,
                            int M, int N, int K, int act) {
    const int BM = 64, BN = 64, BK = 16;
    __shared__ float As[BK][BM];
    __shared__ float Bs[BK][BN + 1];
    int tid = threadIdx.x;
    int row0 = blockIdx.y * BM, col0 = blockIdx.x * BN;
    int ty = tid >> 4, tx = tid & 15;
    float acc[4][4];
    #pragma unroll
    for (int i = 0; i < 4; i++)
        #pragma unroll
        for (int j = 0; j < 4; j++) acc[i][j] = 0.f;

    for (int k0 = 0; k0 < K; k0 += BK) {
        #pragma unroll
        for (int l = 0; l < 4; l++) {
            int e = tid + l * 256;
            int r = e >> 4, c = e & 15;
            int gr = row0 + r, gc = k0 + c;
            As[c][r] = (gr < M && gc < K) ? A[(long)gr * K + gc] : 0.f;
        }
        #pragma unroll
        for (int l = 0; l < 4; l++) {
            int e = tid + l * 256;
            int r = e >> 6, c = e & 63;
            int gr = k0 + r, gc = col0 + c;
            Bs[r][c] = (gr < K && gc < N) ? Bm[(long)gr * N + gc] : 0.f;
        }
        __syncthreads();
        #pragma unroll
        for (int kk = 0; kk < BK; kk++) {
            float a[4], b[4];
            #pragma unroll
            for (int i = 0; i < 4; i++) a[i] = As[kk][ty * 4 + i];
            #pragma unroll
            for (int j = 0; j < 4; j++) b[j] = Bs[kk][tx * 4 + j];
            #pragma unroll
            for (int i = 0; i < 4; i++)
                #pragma unroll
                for (int j = 0; j < 4; j++) acc[i][j] += a[i] * b[j];
        }
        __syncthreads();
    }
    #pragma unroll
    for (int i = 0; i < 4; i++) {
        int r = row0 + ty * 4 + i;
        if (r >= M) continue;
        #pragma unroll
        for (int j = 0; j < 4; j++) {
            int c = col0 + tx * 4 + j;
            if (c >= N) continue;
            float v = acc[i][j];
            if (bias) v += bias[c];
            if (residual) v += residual[(long)r * N + c];
            if (act) v = fmaxf(v, 0.f);
            C[(long)r * N + c] = v;
        }
    }
}

// ---------------- score head (GEMV over 128) ----------------
__global__ void score_kernel(const float* __restrict__ Hd, const float* __restrict__ W2,
                             const float* __restrict__ b2, float* __restrict__ sc) {
    int row = blockIdx.x * 8 + (threadIdx.x >> 5);
    int lane = threadIdx.x & 31;
    const float* h = Hd + (long)row * 128;
    float s = 0.f;
    for (int c = lane; c < 128; c += 32) s += h[c] * W2[c];
    #pragma unroll
    for (int o = 16; o > 0; o >>= 1) s += __shfl_down_sync(0xffffffffu, s, o);
    if (lane == 0) sc[row] = s + b2[0];
}

// ---------------- top-k via bitonic sort (descending), k = 1024 of 4096 ----------------
__global__ void __launch_bounds__(1024) topk_kernel(const float* __restrict__ score,
                                                    int* __restrict__ idxo) {
    __shared__ float key[4096];
    __shared__ int val[4096];
    int b = blockIdx.x;
    int t = threadIdx.x;
    for (int i = t; i < 4096; i += 1024) { key[i] = score[b * 4096 + i]; val[i] = i; }
    __syncthreads();
    for (int k = 2; k <= 4096; k <<= 1) {
        for (int j = k >> 1; j > 0; j >>= 1) {
            for (int i = t; i < 4096; i += 1024) {
                int ixj = i ^ j;
                if (ixj > i) {
                    bool desc = ((i & k) == 0);
                    float a = key[i], c = key[ixj];
                    bool sw = desc ? (a < c) : (a > c);
                    if (sw) {
                        key[i] = c; key[ixj] = a;
                        int tv = val[i]; val[i] = val[ixj]; val[ixj] = tv;
                    }
                }
            }
            __syncthreads();
        }
    }
    if (t < 1024) idxo[b * 1024 + t] = val[t];
}

// ---------------- gather / scatter selected tokens ----------------
__device__ __forceinline__ long patch_pixel(int b, int n, int t) {
    int hy = n >> 6, wx = n & 63;
    int c = t >> 4, py = (t >> 2) & 3, px = t & 3;
    return (((long)(b * 64 + c) * 256) + hy * 4 + py) * 256 + wx * 4 + px;
}

__global__ void gather_kernel(const float* __restrict__ mapV, const float* __restrict__ mapI,
                              const int* __restrict__ idx,
                              float* __restrict__ selV, float* __restrict__ selI) {
    long gid = (long)blockIdx.x * 256 + threadIdx.x;  // 4096*1024 total
    int bi = (int)(gid >> 10);
    int t = (int)(gid & 1023);
    int b = bi >> 10;
    int n = idx[bi];
    long m = patch_pixel(b, n, t);
    selV[gid] = mapV[m];
    selI[gid] = mapI[m];
}

__global__ void scatter_kernel(const float* __restrict__ fs, const int* __restrict__ idx,
                               float* __restrict__ outMap) {
    long gid = (long)blockIdx.x * 256 + threadIdx.x;
    int bi = (int)(gid >> 10);
    int t = (int)(gid & 1023);
    int b = bi >> 10;
    int n = idx[bi];
    long m = patch_pixel(b, n, t);
    outMap[m] = fs[gid];
}

// ---------------- attention ----------------
__global__ void attn_scores_kernel(const float* __restrict__ Q, const float* __restrict__ Kt,
                                   float* __restrict__ S) {
    __shared__ float Qs[64][33];
    __shared__ float Ks[64][33];
    int z = blockIdx.z;
    int b = z >> 2, h = z & 3;
    const float* Qp = Q + (long)b * 1024 * 128 + h * 32;
    const float* Kp = Kt + (long)b * 1024 * 128 + h * 32;
    int i0 = blockIdx.y * 64, j0 = blockIdx.x * 64;
    int tid = threadIdx.x;
    #pragma unroll
    for (int l = 0; l < 8; l++) {
        int e = tid + l * 256;
        int r = e >> 5, c = e & 31;
        Qs[r][c] = Qp[(long)(i0 + r) * 128 + c];
        Ks[r][c] = Kp[(long)(j0 + r) * 128 + c];
    }
    __syncthreads();
    int ty = tid >> 4, tx = tid & 15;
    float acc[4][4];
    #pragma unroll
    for (int i = 0; i < 4; i++)
        #pragma unroll
        for (int j = 0; j < 4; j++) acc[i][j] = 0.f;
    #pragma unroll
    for (int d = 0; d < 32; d++) {
        float a[4], bb[4];
        #pragma unroll
        for (int i = 0; i < 4; i++) a[i] = Qs[ty * 4 + i][d];
        #pragma unroll
        for (int j = 0; j < 4; j++) bb[j] = Ks[tx * 4 + j][d];
        #pragma unroll
        for (int i = 0; i < 4; i++)
            #pragma unroll
            for (int j = 0; j < 4; j++) acc[i][j] += a[i] * bb[j];
    }
    const float scale = 0.17677669529663687f;  // 1/sqrt(32)
    #pragma unroll
    for (int i = 0; i < 4; i++)
        #pragma unroll
        for (int j = 0; j < 4; j++)
            S[((long)z * 1024 + i0 + ty * 4 + i) * 1024 + j0 + tx * 4 + j] = acc[i][j] * scale;
}

__global__ void softmax_kernel(float* __restrict__ S) {
    __shared__ float red[256];
    long base = ((long)blockIdx.y * 1024 + blockIdx.x) * 1024;
    int t = threadIdx.x;
    float v[4];
    float m = -3.4e38f;
    #pragma unroll
    for (int l = 0; l < 4; l++) { v[l] = S[base + t + l * 256]; m = fmaxf(m, v[l]); }
    red[t] = m;
    __syncthreads();
    for (int s = 128; s > 0; s >>= 1) {
        if (t < s) red[t] = fmaxf(red[t], red[t + s]);
        __syncthreads();
    }
    m = red[0];
    __syncthreads();
    float sum = 0.f;
    #pragma unroll
    for (int l = 0; l < 4; l++) { v[l] = expf(v[l] - m); sum += v[l]; }
    red[t] = sum;
    __syncthreads();
    for (int s = 128; s > 0; s >>= 1) {
        if (t < s) red[t] += red[t + s];
        __syncthreads();
    }
    float inv = 1.0f / red[0];
    #pragma unroll
    for (int l = 0; l < 4; l++) S[base + t + l * 256] = v[l] * inv;
}

__global__ void attn_apply_kernel(const float* __restrict__ S, const float* __restrict__ V,
                                  float* __restrict__ O) {
    __shared__ float Ps[64][65];
    __shared__ float Vs[64][33];
    int z = blockIdx.y;
    int b = z >> 2, h = z & 3;
    int i0 = blockIdx.x * 64;
    int tid = threadIdx.x;
    int ty = tid >> 5, tx = tid & 31;
    float acc[8];
    #pragma unroll
    for (int q = 0; q < 8; q++) acc[q] = 0.f;
    for (int j0 = 0; j0 < 1024; j0 += 64) {
        #pragma unroll
        for (int l = 0; l < 16; l++) {
            int e = tid + l * 256;
            int r = e >> 6, c = e & 63;
            Ps[r][c] = S[((long)z * 1024 + i0 + r) * 1024 + j0 + c];
        }
        #pragma unroll
        for (int l = 0; l < 8; l++) {
            int e = tid + l * 256;
            int r = e >> 5, c = e & 31;
            Vs[r][c] = V[(long)(b * 1024 + j0 + r) * 128 + h * 32 + c];
        }
        __syncthreads();
        #pragma unroll
        for (int kk = 0; kk < 64; kk++) {
            float vv = Vs[kk][tx];
            #pragma unroll
            for (int q = 0; q < 8; q++) acc[q] += Ps[ty * 8 + q][kk] * vv;
        }
        __syncthreads();
    }
    #pragma unroll
    for (int q = 0; q < 8; q++)
        O[(long)(b * 1024 + i0 + ty * 8 + q) * 128 + h * 32 + tx] = acc[q];
}

// ---------------- elementwise ----------------
__global__ void avg_kernel(const float* __restrict__ a, const float* __restrict__ b,
                           float* __restrict__ o) {
    int i = blockIdx.x * 256 + threadIdx.x;
    o[i] = 0.5f * (a[i] + b[i]);
}

__global__ void combine_kernel(const float* __restrict__ fa, const float* __restrict__ fp,
                               float2* __restrict__ c) {
    int i = blockIdx.x * 256 + threadIdx.x;
    float s, co;
    sincosf(fp[i], &s, &co);
    float a = fa[i];
    c[i] = make_float2(a * co, a * s);
}

// ---------------- 3x3 SAME conv, 64->64 channels ----------------
__global__ void conv3_kernel(const float* __restrict__ in, const float* __restrict__ wgt,
                             const float* __restrict__ bias, float* __restrict__ out,
                             const float* __restrict__ resA, const float* __restrict__ resB,
                             int relu) {
    __shared__ float sIn[18][18];
    __shared__ float sW[64 * 9];
    int bz = blockIdx.z;
    int x0 = blockIdx.x * 16, y0 = blockIdx.y * 16;
    int tx = threadIdx.x, ty = threadIdx.y;
    int tid = ty * 16 + tx;
    int x = x0 + tx, y = y0 + ty;
    float acc[64];
    #pragma unroll
    for (int co = 0; co < 64; co++) acc[co] = 0.f;

    for (int ci = 0; ci < 64; ci++) {
        const float* ip = in + (long)(bz * 64 + ci) * 65536;
        for (int e = tid; e < 324; e += 256) {
            int ry = e / 18, rx = e % 18;
            int gy = y0 + ry - 1, gx = x0 + rx - 1;
            sIn[ry][rx] = (gy >= 0 && gy < 256 && gx >= 0 && gx < 256) ? ip[gy * 256 + gx] : 0.f;
        }
        for (int e = tid; e < 576; e += 256)
            sW[e] = wgt[(long)( (e / 9) * 64 + ci) * 9 + (e % 9)];
        __syncthreads();
        float v[9];
        #pragma unroll
        for (int ky = 0; ky < 3; ky++)
            #pragma unroll
            for (int kx = 0; kx < 3; kx++) v[ky * 3 + kx] = sIn[ty + ky][tx + kx];
        #pragma unroll
        for (int co = 0; co < 64; co++) {
            float s = acc[co];
            #pragma unroll
            for (int k = 0; k < 9; k++) s += v[k] * sW[co * 9 + k];
            acc[co] = s;
        }
        __syncthreads();
    }
    #pragma unroll
    for (int co = 0; co < 64; co++) {
        long oidx = ((long)(bz * 64 + co) * 256 + y) * 256 + x;
        float vv = acc[co] + bias[co];
        if (relu) vv = fmaxf(vv, 0.f);
        if (resA) vv += 0.5f * (resA[oidx] + resB[oidx]);
        out[oidx] = vv;
    }
}

// ---------------- host-side branch driver ----------------
static void run_branch(const float* mapV, const float* mapI,
                       const float* W1, const float* b1,
                       const float* W2, const float* b2,
                       const float* Wq, const float* Wk, const float* Wv, const float* Wo,
                       const float* intent,
                       float* feat, float* hid, float* score, int* idxp,
                       float* selV, float* selI,
                       float* q, float* k, float* v, float* o,
                       float* att, float* fs, float* outMap) {
    feat_kernel<<<dim3(9, NT_), 256>>>(mapV, mapI, intent, feat);
    gemm_kernel<<<dim3(2, 256), 256>>>(feat, W1, hid, b1, nullptr, NT_, 128, SF_, 1);
    score_kernel<<<2048, 256>>>(hid, W2, b2, score);
    topk_kernel<<<4, 1024>>>(score, idxp);
    gather_kernel<<<16384, 256>>>(mapV, mapI, idxp, selV, selI);
    gemm_kernel<<<dim3(2, 64), 256>>>(selV, Wq, q, nullptr, nullptr, 4096, 128, 1024, 0);
    gemm_kernel<<<dim3(2, 64), 256>>>(selI, Wk, k, nullptr, nullptr, 4096, 128, 1024, 0);
    gemm_kernel<<<dim3(2, 64), 256>>>(selI, Wv, v, nullptr, nullptr, 4096, 128, 1024, 0);
    attn_scores_kernel<<<dim3(16, 16, 16), 256>>>(q, k, att);
    softmax_kernel<<<dim3(1024, 16), 256>>>(att);
    attn_apply_kernel<<<dim3(16, 16), 256>>>(att, v, o);
    gemm_kernel<<<dim3(16, 64), 256>>>(o, Wo, fs, nullptr, selV, 4096, 1024, 128, 0);
    avg_kernel<<<65536, 256>>>(mapV, mapI, outMap);
    scatter_kernel<<<16384, 256>>>(fs, idxp, outMap);
}

extern "C" void kernel_launch(void* const* d_in, const int* in_sizes, int n_in,
                              void* d_out, int out_size) {
    const float* vis  = (const float*)d_in[0];
    const float* ir   = (const float*)d_in[1];
    const float* bank = (const float*)d_in[2];
    const float* Wr   = (const float*)d_in[3];
    const float* br   = (const float*)d_in[4];
    const float* aW1  = (const float*)d_in[5];
    const float* ab1  = (const float*)d_in[6];
    const float* aW2  = (const float*)d_in[7];
    const float* ab2  = (const float*)d_in[8];
    const float* aWq  = (const float*)d_in[9];
    const float* aWk  = (const float*)d_in[10];
    const float* aWv  = (const float*)d_in[11];
    const float* aWo  = (const float*)d_in[12];
    const float* pW1  = (const float*)d_in[13];
    const float* pb1  = (const float*)d_in[14];
    const float* pW2  = (const float*)d_in[15];
    const float* pb2  = (const float*)d_in[16];
    const float* pWq  = (const float*)d_in[17];
    const float* pWk  = (const float*)d_in[18];
    const float* pWv  = (const float*)d_in[19];
    const float* pWo  = (const float*)d_in[20];
    const float* c1w  = (const float*)d_in[21];
    const float* c1b  = (const float*)d_in[22];
    const float* c2w  = (const float*)d_in[23];
    const float* c2b  = (const float*)d_in[24];
    float* out = (float*)d_out;

    float2 *cA, *cB;
    float *ampV, *ampI, *phV, *phI, *faMap, *fpMap, *spatial, *r1;
    float *feat, *hid, *score, *selV, *selI, *q, *k, *v, *o, *att, *fs, *gm, *intent;
    int* idxp;
    cudaGetSymbolAddress((void**)&cA, g_cA);
    cudaGetSymbolAddress((void**)&cB, g_cB);
    cudaGetSymbolAddress((void**)&ampV, g_ampV);
    cudaGetSymbolAddress((void**)&ampI, g_ampI);
    cudaGetSymbolAddress((void**)&phV, g_phV);
    cudaGetSymbolAddress((void**)&phI, g_phI);
    cudaGetSymbolAddress((void**)&faMap, g_faMap);
    cudaGetSymbolAddress((void**)&fpMap, g_fpMap);
    cudaGetSymbolAddress((void**)&spatial, g_spatial);
    cudaGetSymbolAddress((void**)&r1, g_r1);
    cudaGetSymbolAddress((void**)&feat, g_feat);
    cudaGetSymbolAddress((void**)&hid, g_hid);
    cudaGetSymbolAddress((void**)&score, g_scoreArr);
    cudaGetSymbolAddress((void**)&idxp, g_idxArr);
    cudaGetSymbolAddress((void**)&selV, g_selV);
    cudaGetSymbolAddress((void**)&selI, g_selI);
    cudaGetSymbolAddress((void**)&q, g_qb);
    cudaGetSymbolAddress((void**)&k, g_kb);
    cudaGetSymbolAddress((void**)&v, g_vb);
    cudaGetSymbolAddress((void**)&o, g_ob);
    cudaGetSymbolAddress((void**)&att, g_att);
    cudaGetSymbolAddress((void**)&fs, g_fs);
    cudaGetSymbolAddress((void**)&gm, g_gm);
    cudaGetSymbolAddress((void**)&intent, g_intentArr);

    // twiddles + router
    twiddle_init_kernel<<<1, 128>>>();
    gap_kernel<<<512, 256>>>(vis, ir, gm);
    router_kernel<<<1, 64>>>(gm, Wr, br, bank, intent);

    // forward 2D FFTs (rows then cols) of both modalities
    const int FFT_BLOCKS = (B_ * C_ * 256) / 2;   // 131072
    fft_pass_kernel<<<FFT_BLOCKS, 256>>>(cA, vis, nullptr, +1, 0);
    fft_pass_kernel<<<FFT_BLOCKS, 256>>>(cA, nullptr, nullptr, +1, 1);
    fft_pass_kernel<<<FFT_BLOCKS, 256>>>(cB, ir, nullptr, +1, 0);
    fft_pass_kernel<<<FFT_BLOCKS, 256>>>(cB, nullptr, nullptr, +1, 1);
    ampphase_kernel<<<65536, 256>>>();

    // amplitude branch
    run_branch(ampV, ampI, aW1, ab1, aW2, ab2, aWq, aWk, aWv, aWo, intent,
               feat, hid, score, idxp, selV, selI, q, k, v, o, att, fs, faMap);
    // phase branch
    run_branch(phV, phI, pW1, pb1, pW2, pb2, pWq, pWk, pWv, pWo, intent,
               feat, hid, score, idxp, selV, selI, q, k, v, o, att, fs, fpMap);

    // recombine (phase wrap is a no-op under exp(i*phi)) and inverse 2D FFT
    combine_kernel<<<65536, 256>>>(faMap, fpMap, cA);
    fft_pass_kernel<<<FFT_BLOCKS, 256>>>(cA, nullptr, nullptr, -1, 0);
    fft_pass_kernel<<<FFT_BLOCKS, 256>>>(cA, nullptr, spatial, -1, 1);

    // conv head + global residual
    conv3_kernel<<<dim3(16, 16, 4), dim3(16, 16)>>>(spatial, c1w, c1b, r1, nullptr, nullptr, 1);
    conv3_kernel<<<dim3(16, 16, 4), dim3(16, 16)>>>(r1, c2w, c2b, out, vis, ir, 0);

    (void)in_sizes; (void)n_in; (void)out_size;
}

// round 2
// speedup vs baseline: 1.3681x; 1.3681x over previous
#include <cuda_runtime.h>
#include <math.h>

// ---------------- problem constants ----------------
#define B_    4
#define C_    64
#define H_    256
#define W_    256
#define NPIX_ 16777216            // B*C*H*W
#define NPAT_ 4096                // patches per batch (64*64)
#define NT_   16384               // B * NPAT
#define TOK_  1024
#define SF_   2114
#define KSEL_ 1024
#define E_    128

// ---------------- device scratch (static; no runtime allocation) ----------------
__device__ float2 g_cA[NPIX_];
__device__ float  g_ampV[NPIX_];
__device__ float  g_ampI[NPIX_];
__device__ float  g_phV [NPIX_];
__device__ float  g_phI [NPIX_];
__device__ float  g_faMap[NPIX_];
__device__ float  g_fpMap[NPIX_];
__device__ float  g_spatial[NPIX_];
__device__ float  g_r1[NPIX_];
__device__ float  g_scoreArr[NT_];
__device__ int    g_idxArr[B_ * KSEL_];
__device__ float  g_selV[(long)B_ * KSEL_ * TOK_];
__device__ float  g_selI[(long)B_ * KSEL_ * TOK_];
__device__ float  g_qb[B_ * KSEL_ * E_];
__device__ float  g_kb[B_ * KSEL_ * E_];
__device__ float  g_vb[B_ * KSEL_ * E_];
__device__ float  g_ob[B_ * KSEL_ * E_];
__device__ float  g_att[(long)B_ * 4 * KSEL_ * KSEL_];
__device__ float  g_fs[(long)B_ * KSEL_ * TOK_];
__device__ float  g_gm[B_ * 2 * C_];
__device__ float  g_intentArr[B_ * 64];
__device__ float  g_t256r[256];
__device__ float  g_t256i[256];

// ---------------- twiddles ----------------
__global__ void twiddle_init_kernel() {
    int k = threadIdx.x;  // 256 threads
    double a = -2.0 * 3.14159265358979323846 * (double)k / 256.0;
    g_t256r[k] = (float)cos(a);
    g_t256i[k] = (float)sin(a);
}

// ---------------- 16-point register FFT (DIT radix-2, fully unrolled) ----------------
__device__ __forceinline__ void fft16_reg(float* xr, float* xi, float dsign) {
    #define SW16_(a,b) { float t=xr[a]; xr[a]=xr[b]; xr[b]=t; t=xi[a]; xi[a]=xi[b]; xi[b]=t; }
    SW16_(1,8) SW16_(2,4) SW16_(3,12) SW16_(5,10) SW16_(7,14) SW16_(11,13)
    #undef SW16_
    const float C16[8] = {1.f, 0.9238795325112867f, 0.7071067811865476f, 0.3826834323650898f,
                          0.f, -0.3826834323650898f, -0.7071067811865476f, -0.9238795325112867f};
    const float S16[8] = {0.f, 0.3826834323650898f, 0.7071067811865476f, 0.9238795325112867f,
                          1.f, 0.9238795325112867f, 0.7071067811865476f, 0.3826834323650898f};
    #pragma unroll
    for (int s = 1; s <= 4; s++) {
        const int half = 1 << (s - 1);
        #pragma unroll
        for (int j = 0; j < 8; j++) {
            const int grp = j >> (s - 1);
            const int pos = j & (half - 1);
            const int i = (grp << s) + pos;
            const int l = i + half;
            const int ti = pos << (4 - s);
            float wr = C16[ti];
            float wi = -dsign * S16[ti];
            float vr = xr[l] * wr - xi[l] * wi;
            float vi = xr[l] * wi + xi[l] * wr;
            float ur = xr[i], ui = xi[i];
            xr[i] = ur + vr; xi[i] = ui + vi;
            xr[l] = ur - vr; xi[l] = ui - vi;
        }
    }
}

// ---------------- 256-pt FFT pass: four-step, 16 threads/FFT, 16 FFTs/block ----------------
// input modes:  rin != null  -> real input
//               fa  != null  -> amp/phase recombine (fa*cos(fp), fa*sin(fp))
//               else         -> complex from cin
// output modes: cout != null -> complex
//               amp  != null -> amplitude + phase (atan2)
//               else         -> real part only (scaled)
#define FFT_SM 4352
__global__ void fft_pass2_kernel(const float2* __restrict__ cin,
                                 const float* __restrict__ rin,
                                 const float* __restrict__ fa,
                                 const float* __restrict__ fp,
                                 float2* __restrict__ cout,
                                 float* __restrict__ amp,
                                 float* __restrict__ ph,
                                 float* __restrict__ rout,
                                 int colmode, int dir, float scale) {
    __shared__ float sre[FFT_SM];
    __shared__ float sim[FFT_SM];
    int tid = threadIdx.x;
    int tx = tid & 15, ty = tid >> 4;
    int u = colmode ? ty : tx;   // within-FFT thread index
    int s = colmode ? tx : ty;   // FFT slot within block
    int line = blockIdx.x * 16 + s;
    int plane = line >> 8, l = line & 255;
    long base; int stride;
    if (colmode) { base = (long)plane * 65536 + l; stride = 256; }
    else         { base = (long)plane * 65536 + (long)l * 256; stride = 1; }
    float dsign = (dir > 0) ? 1.f : -1.f;

    float xr[16], xi[16];
    #pragma unroll
    for (int n2 = 0; n2 < 16; n2++) {
        long a = base + (long)(u + 16 * n2) * stride;
        if (rin)      { xr[n2] = rin[a]; xi[n2] = 0.f; }
        else if (fa)  { float am = fa[a]; float sn, cs; sincosf(fp[a], &sn, &cs);
                        xr[n2] = am * cs; xi[n2] = am * sn; }
        else          { float2 c = cin[a]; xr[n2] = c.x; xi[n2] = c.y; }
    }
    fft16_reg(xr, xi, dsign);
    // inter-stage twiddle W256^{u*k2}
    #pragma unroll
    for (int k2 = 0; k2 < 16; k2++) {
        int m = u * k2;
        float wr = g_t256r[m];
        float wi = dsign * g_t256i[m];
        float a = xr[k2], b = xi[k2];
        xr[k2] = a * wr - b * wi;
        xi[k2] = a * wi + b * wr;
    }
    #pragma unroll
    for (int k2 = 0; k2 < 16; k2++) {
        int idx = colmode ? ((k2 * 16 + u) * 17 + s) : (s * 272 + k2 * 17 + u);
        sre[idx] = xr[k2]; sim[idx] = xi[k2];
    }
    __syncthreads();
    #pragma unroll
    for (int n1 = 0; n1 < 16; n1++) {
        int idx = colmode ? ((u * 16 + n1) * 17 + s) : (s * 272 + u * 17 + n1);
        xr[n1] = sre[idx]; xi[n1] = sim[idx];
    }
    fft16_reg(xr, xi, dsign);
    #pragma unroll
    for (int k1 = 0; k1 < 16; k1++) {
        long a = base + (long)(16 * k1 + u) * stride;
        float rr = xr[k1] * scale, ii = xi[k1] * scale;
        if (cout)      cout[a] = make_float2(rr, ii);
        else if (amp)  { amp[a] = sqrtf(rr * rr + ii * ii); ph[a] = atan2f(ii, rr); }
        else           rout[a] = rr;
    }
}

// ---------------- router ----------------
__global__ void gap_kernel(const float* __restrict__ vis, const float* __restrict__ ir,
                           float* __restrict__ gm) {
    __shared__ float red[256];
    int b = blockIdx.x >> 7;
    int ch = blockIdx.x & 127;
    const float* p = (ch < 64) ? (vis + (long)(b * 64 + ch) * 65536)
                               : (ir  + (long)(b * 64 + ch - 64) * 65536);
    float s = 0.f;
    for (int i = threadIdx.x; i < 65536; i += 256) s += p[i];
    red[threadIdx.x] = s;
    __syncthreads();
    for (int st = 128; st > 0; st >>= 1) {
        if (threadIdx.x < st) red[threadIdx.x] += red[threadIdx.x + st];
        __syncthreads();
    }
    if (threadIdx.x == 0) gm[blockIdx.x] = red[0] * (1.0f / 65536.0f);
}

__global__ void router_kernel(const float* __restrict__ gm, const float* __restrict__ Wr,
                              const float* __restrict__ br, const float* __restrict__ bank,
                              float* __restrict__ intent) {
    __shared__ float pf[4][64];
    __shared__ float lg[4][4];
    __shared__ float w[4][4];
    int t = threadIdx.x;  // 64 threads
    for (int b = 0; b < 4; b++) {
        float s = br[t];
        for (int c = 0; c < 128; c++) s += gm[b * 128 + c] * Wr[c * 64 + t];
        pf[b][t] = s;
    }
    __syncthreads();
    if (t < 16) {
        int b = t >> 2, j = t & 3;
        float s = 0.f;
        for (int p = 0; p < 64; p++) s += pf[b][p] * bank[j * 64 + p];
        lg[b][j] = s;
    }
    __syncthreads();
    if (t < 4) {
        int b = t;
        float m = fmaxf(fmaxf(lg[b][0], lg[b][1]), fmaxf(lg[b][2], lg[b][3]));
        float e0 = expf(lg[b][0] - m), e1 = expf(lg[b][1] - m);
        float e2 = expf(lg[b][2] - m), e3 = expf(lg[b][3] - m);
        float s = e0 + e1 + e2 + e3;
        w[b][0] = e0 / s; w[b][1] = e1 / s; w[b][2] = e2 / s; w[b][3] = e3 / s;
    }
    __syncthreads();
    for (int b = 0; b < 4; b++) {
        float s = 0.f;
        for (int j = 0; j < 4; j++) s += w[b][j] * bank[j * 64 + t];
        intent[b * 64 + t] = s;
    }
}

// ---------------- fused score net: feat-gen + W1 GEMM + ReLU + W2 GEMV ----------------
// Block: 64 tokens x 128 hidden; micro-tile 4x8; epilogue reduces to per-token score.
__global__ void __launch_bounds__(256) score_fused_kernel(
        const float* __restrict__ mapV, const float* __restrict__ mapI,
        const float* __restrict__ intent,
        const float* __restrict__ W1, const float* __restrict__ b1,
        const float* __restrict__ W2, const float* __restrict__ b2,
        float* __restrict__ score) {
    const int BM = 64, BK = 16;
    __shared__ float As[BK][68];     // [k][row], padded
    __shared__ float Bs[BK][132];    // [k][col], padded
    __shared__ float red[64 * 16];
    int tid = threadIdx.x;
    int row0 = blockIdx.x * BM;
    int ty = tid >> 4, tx = tid & 15;

    float acc[4][8];
    #pragma unroll
    for (int i = 0; i < 4; i++)
        #pragma unroll
        for (int j = 0; j < 8; j++) acc[i][j] = 0.f;

    for (int k0 = 0; k0 < SF_; k0 += BK) {
        // A tile: 16x64, generated on the fly (4 elems/thread)
        #pragma unroll
        for (int lq = 0; lq < 4; lq++) {
            int e = tid + lq * 256;          // 0..1023
            int r = e >> 4, c = e & 15;
            int col = k0 + c;
            int tok = row0 + r;
            int b = tok >> 12, n = tok & 4095;
            float v = 0.f;
            if (col < 2048) {
                int t = col & 1023;
                int ch = t >> 4, py = (t >> 2) & 3, px = t & 3;
                int hy = n >> 6, wx = n & 63;
                long m = (((long)(b * 64 + ch) * 256) + hy * 4 + py) * 256 + wx * 4 + px;
                v = (col < 1024) ? mapV[m] : mapI[m];
            } else if (col < SF_) {
                if (col == 2048)      v = (float)(n >> 6) * (1.0f / 63.0f);
                else if (col == 2049) v = (float)(n & 63) * (1.0f / 63.0f);
                else                  v = intent[b * 64 + (col - 2050)];
            }
            As[c][r] = v;
        }
        // B tile: 16x128 (8 elems/thread, coalesced)
        #pragma unroll
        for (int lq = 0; lq < 8; lq++) {
            int e = tid + lq * 256;
            int r = e >> 7, c = e & 127;
            Bs[r][c] = (k0 + r < SF_) ? W1[(long)(k0 + r) * 128 + c] : 0.f;
        }
        __syncthreads();
        #pragma unroll
        for (int kk = 0; kk < BK; kk++) {
            float a[4], bb[8];
            float4 av = *(const float4*)&As[kk][ty * 4];
            a[0] = av.x; a[1] = av.y; a[2] = av.z; a[3] = av.w;
            float4 b0 = *(const float4*)&Bs[kk][tx * 8];
            float4 b1v = *(const float4*)&Bs[kk][tx * 8 + 4];
            bb[0] = b0.x; bb[1] = b0.y; bb[2] = b0.z; bb[3] = b0.w;
            bb[4] = b1v.x; bb[5] = b1v.y; bb[6] = b1v.z; bb[7] = b1v.w;
            #pragma unroll
            for (int i = 0; i < 4; i++)
                #pragma unroll
                for (int j = 0; j < 8; j++) acc[i][j] += a[i] * bb[j];
        }
        __syncthreads();
    }

    // epilogue: relu(acc + b1) dot W2, reduced across the 16 column groups
    float w2[8], bs[8];
    #pragma unroll
    for (int j = 0; j < 8; j++) { w2[j] = W2[tx * 8 + j]; bs[j] = b1[tx * 8 + j]; }
    #pragma unroll
    for (int i = 0; i < 4; i++) {
        float p = 0.f;
        #pragma unroll
        for (int j = 0; j < 8; j++) {
            float h = fmaxf(acc[i][j] + bs[j], 0.f);
            p += h * w2[j];
        }
        red[(ty * 4 + i) * 16 + tx] = p;
    }
    __syncthreads();
    if (tid < 64) {
        float s = 0.f;
        #pragma unroll
        for (int q = 0; q < 16; q++) s += red[tid * 16 + q];
        score[row0 + tid] = s + b2[0];
    }
}

// ---------------- generic fp32 GEMM: C = A@B (+bias) (+residual) (+relu) ----------------
__global__ void gemm_kernel(const float* __restrict__ A, const float* __restrict__ Bm,
                            float* __restrict__ C, const float* __restrict__ bias,
                            const float* __restrict__ residual,
                            int M, int N, int K, int act) {
    const int BM = 64, BN = 64, BK = 16;
    __shared__ float As[BK][BM];
    __shared__ float Bs[BK][BN + 1];
    int tid = threadIdx.x;
    int row0 = blockIdx.y * BM, col0 = blockIdx.x * BN;
    int ty = tid >> 4, tx = tid & 15;
    float acc[4][4];
    #pragma unroll
    for (int i = 0; i < 4; i++)
        #pragma unroll
        for (int j = 0; j < 4; j++) acc[i][j] = 0.f;

    for (int k0 = 0; k0 < K; k0 += BK) {
        #pragma unroll
        for (int l = 0; l < 4; l++) {
            int e = tid + l * 256;
            int r = e >> 4, c = e & 15;
            int gr = row0 + r, gc = k0 + c;
            As[c][r] = (gr < M && gc < K) ? A[(long)gr * K + gc] : 0.f;
        }
        #pragma unroll
        for (int l = 0; l < 4; l++) {
            int e = tid + l * 256;
            int r = e >> 6, c = e & 63;
            int gr = k0 + r, gc = col0 + c;
            Bs[r][c] = (gr < K && gc < N) ? Bm[(long)gr * N + gc] : 0.f;
        }
        __syncthreads();
        #pragma unroll
        for (int kk = 0; kk < BK; kk++) {
            float a[4], b[4];
            #pragma unroll
            for (int i = 0; i < 4; i++) a[i] = As[kk][ty * 4 + i];
            #pragma unroll
            for (int j = 0; j < 4; j++) b[j] = Bs[kk][tx * 4 + j];
            #pragma unroll
            for (int i = 0; i < 4; i++)
                #pragma unroll
                for (int j = 0; j < 4; j++) acc[i][j] += a[i] * b[j];
        }
        __syncthreads();
    }
    #pragma unroll
    for (int i = 0; i < 4; i++) {
        int r = row0 + ty * 4 + i;
        if (r >= M) continue;
        #pragma unroll
        for (int j = 0; j < 4; j++) {
            int c = col0 + tx * 4 + j;
            if (c >= N) continue;
            float v = acc[i][j];
            if (bias) v += bias[c];
            if (residual) v += residual[(long)r * N + c];
            if (act) v = fmaxf(v, 0.f);
            C[(long)r * N + c] = v;
        }
    }
}

// ---------------- top-k via bitonic sort (descending), k = 1024 of 4096 ----------------
__global__ void __launch_bounds__(1024) topk_kernel(const float* __restrict__ score,
                                                    int* __restrict__ idxo) {
    __shared__ float key[4096];
    __shared__ int val[4096];
    int b = blockIdx.x;
    int t = threadIdx.x;
    for (int i = t; i < 4096; i += 1024) { key[i] = score[b * 4096 + i]; val[i] = i; }
    __syncthreads();
    for (int k = 2; k <= 4096; k <<= 1) {
        for (int j = k >> 1; j > 0; j >>= 1) {
            for (int i = t; i < 4096; i += 1024) {
                int ixj = i ^ j;
                if (ixj > i) {
                    bool desc = ((i & k) == 0);
                    float a = key[i], c = key[ixj];
                    bool sw = desc ? (a < c) : (a > c);
                    if (sw) {
                        key[i] = c; key[ixj] = a;
                        int tv = val[i]; val[i] = val[ixj]; val[ixj] = tv;
                    }
                }
            }
            __syncthreads();
        }
    }
    if (t < 1024) idxo[b * 1024 + t] = val[t];
}

// ---------------- gather / scatter selected tokens ----------------
__device__ __forceinline__ long patch_pixel(int b, int n, int t) {
    int hy = n >> 6, wx = n & 63;
    int c = t >> 4, py = (t >> 2) & 3, px = t & 3;
    return (((long)(b * 64 + c) * 256) + hy * 4 + py) * 256 + wx * 4 + px;
}

__global__ void gather_kernel(const float* __restrict__ mapV, const float* __restrict__ mapI,
                              const int* __restrict__ idx,
                              float* __restrict__ selV, float* __restrict__ selI) {
    long gid = (long)blockIdx.x * 256 + threadIdx.x;
    int bi = (int)(gid >> 10);
    int t = (int)(gid & 1023);
    int b = bi >> 10;
    int n = idx[bi];
    long m = patch_pixel(b, n, t);
    selV[gid] = mapV[m];
    selI[gid] = mapI[m];
}

__global__ void scatter_kernel(const float* __restrict__ fs, const int* __restrict__ idx,
                               float* __restrict__ outMap) {
    long gid = (long)blockIdx.x * 256 + threadIdx.x;
    int bi = (int)(gid >> 10);
    int t = (int)(gid & 1023);
    int b = bi >> 10;
    int n = idx[bi];
    long m = patch_pixel(b, n, t);
    outMap[m] = fs[gid];
}

// ---------------- attention ----------------
__global__ void attn_scores_kernel(const float* __restrict__ Q, const float* __restrict__ Kt,
                                   float* __restrict__ S) {
    __shared__ float Qs[64][33];
    __shared__ float Ks[64][33];
    int z = blockIdx.z;
    int b = z >> 2, h = z & 3;
    const float* Qp = Q + (long)b * 1024 * 128 + h * 32;
    const float* Kp = Kt + (long)b * 1024 * 128 + h * 32;
    int i0 = blockIdx.y * 64, j0 = blockIdx.x * 64;
    int tid = threadIdx.x;
    #pragma unroll
    for (int l = 0; l < 8; l++) {
        int e = tid + l * 256;
        int r = e >> 5, c = e & 31;
        Qs[r][c] = Qp[(long)(i0 + r) * 128 + c];
        Ks[r][c] = Kp[(long)(j0 + r) * 128 + c];
    }
    __syncthreads();
    int ty = tid >> 4, tx = tid & 15;
    float acc[4][4];
    #pragma unroll
    for (int i = 0; i < 4; i++)
        #pragma unroll
        for (int j = 0; j < 4; j++) acc[i][j] = 0.f;
    #pragma unroll
    for (int d = 0; d < 32; d++) {
        float a[4], bb[4];
        #pragma unroll
        for (int i = 0; i < 4; i++) a[i] = Qs[ty * 4 + i][d];
        #pragma unroll
        for (int j = 0; j < 4; j++) bb[j] = Ks[tx * 4 + j][d];
        #pragma unroll
        for (int i = 0; i < 4; i++)
            #pragma unroll
            for (int j = 0; j < 4; j++) acc[i][j] += a[i] * bb[j];
    }
    const float scale = 0.17677669529663687f;
    #pragma unroll
    for (int i = 0; i < 4; i++)
        #pragma unroll
        for (int j = 0; j < 4; j++)
            S[((long)z * 1024 + i0 + ty * 4 + i) * 1024 + j0 + tx * 4 + j] = acc[i][j] * scale;
}

__global__ void softmax_kernel(float* __restrict__ S) {
    __shared__ float red[256];
    long base = ((long)blockIdx.y * 1024 + blockIdx.x) * 1024;
    int t = threadIdx.x;
    float v[4];
    float m = -3.4e38f;
    #pragma unroll
    for (int l = 0; l < 4; l++) { v[l] = S[base + t + l * 256]; m = fmaxf(m, v[l]); }
    red[t] = m;
    __syncthreads();
    for (int s = 128; s > 0; s >>= 1) {
        if (t < s) red[t] = fmaxf(red[t], red[t + s]);
        __syncthreads();
    }
    m = red[0];
    __syncthreads();
    float sum = 0.f;
    #pragma unroll
    for (int l = 0; l < 4; l++) { v[l] = expf(v[l] - m); sum += v[l]; }
    red[t] = sum;
    __syncthreads();
    for (int s = 128; s > 0; s >>= 1) {
        if (t < s) red[t] += red[t + s];
        __syncthreads();
    }
    float inv = 1.0f / red[0];
    #pragma unroll
    for (int l = 0; l < 4; l++) S[base + t + l * 256] = v[l] * inv;
}

__global__ void attn_apply_kernel(const float* __restrict__ S, const float* __restrict__ V,
                                  float* __restrict__ O) {
    __shared__ float Ps[64][65];
    __shared__ float Vs[64][33];
    int z = blockIdx.y;
    int b = z >> 2, h = z & 3;
    int i0 = blockIdx.x * 64;
    int tid = threadIdx.x;
    int ty = tid >> 5, tx = tid & 31;
    float acc[8];
    #pragma unroll
    for (int q = 0; q < 8; q++) acc[q] = 0.f;
    for (int j0 = 0; j0 < 1024; j0 += 64) {
        #pragma unroll
        for (int l = 0; l < 16; l++) {
            int e = tid + l * 256;
            int r = e >> 6, c = e & 63;
            Ps[r][c] = S[((long)z * 1024 + i0 + r) * 1024 + j0 + c];
        }
        #pragma unroll
        for (int l = 0; l < 8; l++) {
            int e = tid + l * 256;
            int r = e >> 5, c = e & 31;
            Vs[r][c] = V[(long)(b * 1024 + j0 + r) * 128 + h * 32 + c];
        }
        __syncthreads();
        #pragma unroll
        for (int kk = 0; kk < 64; kk++) {
            float vv = Vs[kk][tx];
            #pragma unroll
            for (int q = 0; q < 8; q++) acc[q] += Ps[ty * 8 + q][kk] * vv;
        }
        __syncthreads();
    }
    #pragma unroll
    for (int q = 0; q < 8; q++)
        O[(long)(b * 1024 + i0 + ty * 8 + q) * 128 + h * 32 + tx] = acc[q];
}

// ---------------- elementwise avg ----------------
__global__ void avg_kernel(const float* __restrict__ a, const float* __restrict__ b,
                           float* __restrict__ o) {
    int i = blockIdx.x * 256 + threadIdx.x;
    o[i] = 0.5f * (a[i] + b[i]);
}

// ---------------- 3x3 SAME conv, 64->64 channels ----------------
__global__ void conv3_kernel(const float* __restrict__ in, const float* __restrict__ wgt,
                             const float* __restrict__ bias, float* __restrict__ out,
                             const float* __restrict__ resA, const float* __restrict__ resB,
                             int relu) {
    __shared__ float sIn[18][18];
    __shared__ float sW[64 * 9];
    int bz = blockIdx.z;
    int x0 = blockIdx.x * 16, y0 = blockIdx.y * 16;
    int tx = threadIdx.x, ty = threadIdx.y;
    int tid = ty * 16 + tx;
    int x = x0 + tx, y = y0 + ty;
    float acc[64];
    #pragma unroll
    for (int co = 0; co < 64; co++) acc[co] = 0.f;

    for (int ci = 0; ci < 64; ci++) {
        const float* ip = in + (long)(bz * 64 + ci) * 65536;
        for (int e = tid; e < 324; e += 256) {
            int ry = e / 18, rx = e % 18;
            int gy = y0 + ry - 1, gx = x0 + rx - 1;
            sIn[ry][rx] = (gy >= 0 && gy < 256 && gx >= 0 && gx < 256) ? ip[gy * 256 + gx] : 0.f;
        }
        for (int e = tid; e < 576; e += 256)
            sW[e] = wgt[(long)((e / 9) * 64 + ci) * 9 + (e % 9)];
        __syncthreads();
        float v[9];
        #pragma unroll
        for (int ky = 0; ky < 3; ky++)
            #pragma unroll
            for (int kx = 0; kx < 3; kx++) v[ky * 3 + kx] = sIn[ty + ky][tx + kx];
        #pragma unroll
        for (int co = 0; co < 64; co++) {
            float s = acc[co];
            #pragma unroll
            for (int k = 0; k < 9; k++) s += v[k] * sW[co * 9 + k];
            acc[co] = s;
        }
        __syncthreads();
    }
    #pragma unroll
    for (int co = 0; co < 64; co++) {
        long oidx = ((long)(bz * 64 + co) * 256 + y) * 256 + x;
        float vv = acc[co] + bias[co];
        if (relu) vv = fmaxf(vv, 0.f);
        if (resA) vv += 0.5f * (resA[oidx] + resB[oidx]);
        out[oidx] = vv;
    }
}

// ---------------- host-side branch driver ----------------
static void run_branch(const float* mapV, const float* mapI,
                       const float* W1, const float* b1,
                       const float* W2, const float* b2,
                       const float* Wq, const float* Wk, const float* Wv, const float* Wo,
                       const float* intent,
                       float* score, int* idxp,
                       float* selV, float* selI,
                       float* q, float* k, float* v, float* o,
                       float* att, float* fs, float* outMap) {
    score_fused_kernel<<<256, 256>>>(mapV, mapI, intent, W1, b1, W2, b2, score);
    topk_kernel<<<4, 1024>>>(score, idxp);
    gather_kernel<<<16384, 256>>>(mapV, mapI, idxp, selV, selI);
    gemm_kernel<<<dim3(2, 64), 256>>>(selV, Wq, q, nullptr, nullptr, 4096, 128, 1024, 0);
    gemm_kernel<<<dim3(2, 64), 256>>>(selI, Wk, k, nullptr, nullptr, 4096, 128, 1024, 0);
    gemm_kernel<<<dim3(2, 64), 256>>>(selI, Wv, v, nullptr, nullptr, 4096, 128, 1024, 0);
    attn_scores_kernel<<<dim3(16, 16, 16), 256>>>(q, k, att);
    softmax_kernel<<<dim3(1024, 16), 256>>>(att);
    attn_apply_kernel<<<dim3(16, 16), 256>>>(att, v, o);
    gemm_kernel<<<dim3(16, 64), 256>>>(o, Wo, fs, nullptr, selV, 4096, 1024, 128, 0);
    avg_kernel<<<65536, 256>>>(mapV, mapI, outMap);
    scatter_kernel<<<16384, 256>>>(fs, idxp, outMap);
}

extern "C" void kernel_launch(void* const* d_in, const int* in_sizes, int n_in,
                              void* d_out, int out_size) {
    const float* vis  = (const float*)d_in[0];
    const float* ir   = (const float*)d_in[1];
    const float* bank = (const float*)d_in[2];
    const float* Wr   = (const float*)d_in[3];
    const float* br   = (const float*)d_in[4];
    const float* aW1  = (const float*)d_in[5];
    const float* ab1  = (const float*)d_in[6];
    const float* aW2  = (const float*)d_in[7];
    const float* ab2  = (const float*)d_in[8];
    const float* aWq  = (const float*)d_in[9];
    const float* aWk  = (const float*)d_in[10];
    const float* aWv  = (const float*)d_in[11];
    const float* aWo  = (const float*)d_in[12];
    const float* pW1  = (const float*)d_in[13];
    const float* pb1  = (const float*)d_in[14];
    const float* pW2  = (const float*)d_in[15];
    const float* pb2  = (const float*)d_in[16];
    const float* pWq  = (const float*)d_in[17];
    const float* pWk  = (const float*)d_in[18];
    const float* pWv  = (const float*)d_in[19];
    const float* pWo  = (const float*)d_in[20];
    const float* c1w  = (const float*)d_in[21];
    const float* c1b  = (const float*)d_in[22];
    const float* c2w  = (const float*)d_in[23];
    const float* c2b  = (const float*)d_in[24];
    float* out = (float*)d_out;

    float2* cA;
    float *ampV, *ampI, *phV, *phI, *faMap, *fpMap, *spatial, *r1;
    float *score, *selV, *selI, *q, *k, *v, *o, *att, *fs, *gm, *intent;
    int* idxp;
    cudaGetSymbolAddress((void**)&cA, g_cA);
    cudaGetSymbolAddress((void**)&ampV, g_ampV);
    cudaGetSymbolAddress((void**)&ampI, g_ampI);
    cudaGetSymbolAddress((void**)&phV, g_phV);
    cudaGetSymbolAddress((void**)&phI, g_phI);
    cudaGetSymbolAddress((void**)&faMap, g_faMap);
    cudaGetSymbolAddress((void**)&fpMap, g_fpMap);
    cudaGetSymbolAddress((void**)&spatial, g_spatial);
    cudaGetSymbolAddress((void**)&r1, g_r1);
    cudaGetSymbolAddress((void**)&score, g_scoreArr);
    cudaGetSymbolAddress((void**)&idxp, g_idxArr);
    cudaGetSymbolAddress((void**)&selV, g_selV);
    cudaGetSymbolAddress((void**)&selI, g_selI);
    cudaGetSymbolAddress((void**)&q, g_qb);
    cudaGetSymbolAddress((void**)&k, g_kb);
    cudaGetSymbolAddress((void**)&v, g_vb);
    cudaGetSymbolAddress((void**)&o, g_ob);
    cudaGetSymbolAddress((void**)&att, g_att);
    cudaGetSymbolAddress((void**)&fs, g_fs);
    cudaGetSymbolAddress((void**)&gm, g_gm);
    cudaGetSymbolAddress((void**)&intent, g_intentArr);

    // twiddles + router
    twiddle_init_kernel<<<1, 256>>>();
    gap_kernel<<<512, 256>>>(vis, ir, gm);
    router_kernel<<<1, 64>>>(gm, Wr, br, bank, intent);

    const int FB = 4096;   // 65536 lines / 16 per block
    // vis: rows (real->complex), cols (complex -> amp/phase)
    fft_pass2_kernel<<<FB, 256>>>(nullptr, vis, nullptr, nullptr, cA, nullptr, nullptr, nullptr, 0, +1, 1.f);
    fft_pass2_kernel<<<FB, 256>>>(cA, nullptr, nullptr, nullptr, nullptr, ampV, phV, nullptr, 1, +1, 1.f);
    // ir
    fft_pass2_kernel<<<FB, 256>>>(nullptr, ir, nullptr, nullptr, cA, nullptr, nullptr, nullptr, 0, +1, 1.f);
    fft_pass2_kernel<<<FB, 256>>>(cA, nullptr, nullptr, nullptr, nullptr, ampI, phI, nullptr, 1, +1, 1.f);

    // amplitude branch
    run_branch(ampV, ampI, aW1, ab1, aW2, ab2, aWq, aWk, aWv, aWo, intent,
               score, idxp, selV, selI, q, k, v, o, att, fs, faMap);
    // phase branch
    run_branch(phV, phI, pW1, pb1, pW2, pb2, pWq, pWk, pWv, pWo, intent,
               score, idxp, selV, selI, q, k, v, o, att, fs, fpMap);

    // inverse 2D FFT: recombine fa*exp(i*fp) fused into first pass
    fft_pass2_kernel<<<FB, 256>>>(nullptr, nullptr, faMap, fpMap, cA, nullptr, nullptr, nullptr, 0, -1, 1.f);
    fft_pass2_kernel<<<FB, 256>>>(cA, nullptr, nullptr, nullptr, nullptr, nullptr, nullptr, spatial, 1, -1, 1.0f / 65536.0f);

    // conv head + global residual
    conv3_kernel<<<dim3(16, 16, 4), dim3(16, 16)>>>(spatial, c1w, c1b, r1, nullptr, nullptr, 1);
    conv3_kernel<<<dim3(16, 16, 4), dim3(16, 16)>>>(r1, c2w, c2b, out, vis, ir, 0);

    (void)in_sizes; (void)n_in; (void)out_size;
}